// round 7
// baseline (speedup 1.0000x reference)
#include <cuda_runtime.h>
#include <cuda_bf16.h>
#include <cstdint>
#include <math.h>

#define N_NODES 100000
#define N_EDGES 1600000
#define IN_F    512
#define HID     16
#define NCLS    7
#define NB      98            // ceil(N_NODES / 1024) scan tiles
#define G_GEMM  391           // ceil(N_NODES / 256) gemm blocks
#define G1_GEMM 196           // gemm blocks fused with hist
#define HIST_B  2048
#define SCAT_B  2048

// ---------------- scratch (static device globals; no runtime allocation) ----
__device__ float4 g_h1v[N_NODES * 4];      // X@W1, 16 floats/node   (6.4 MB)
__device__ float  g_h2[N_NODES * 8];       // layer-2 features, padded to 8
__device__ float  g_dinv[N_NODES];         // D^-1/2
__device__ int    g_cnt[N_NODES];          // in-degree (excl. self loop)
__device__ int    g_rowptr[N_NODES];       // CSR row starts (by dst)
__device__ int    g_rowfill[N_NODES];      // scatter cursors
__device__ int2   g_edges[N_EDGES];        // {src, bitcast(norm)} grouped by dst
__device__ int    g_is64;                  // edge_index dtype flag
__device__ int    g_bsum[128];             // per-scan-tile sums

// ---------------- f32x2 helpers ---------------------------------------------
__device__ __forceinline__ unsigned long long fma2(unsigned long long a,
                                                   unsigned long long b,
                                                   unsigned long long c) {
    unsigned long long d;
    asm("fma.rn.f32x2 %0, %1, %2, %3;" : "=l"(d) : "l"(a), "l"(b), "l"(c));
    return d;
}
__device__ __forceinline__ unsigned long long bcast2(float v) {
    unsigned long long d;
    asm("mov.b64 %0, {%1, %1};" : "=l"(d) : "f"(v));
    return d;
}
__device__ __forceinline__ float2 unpack2(unsigned long long v) {
    float2 r;
    asm("mov.b64 {%0, %1}, %2;" : "=f"(r.x), "=f"(r.y) : "l"(v));
    return r;
}

// ---------------- GEMM1 block: 256 rows, 256 threads, K chunks of 16 --------
// h1 = X @ W1.  Called from the fused kernels with global gemm block id gbid.
__device__ __forceinline__ void gemm_block(int gbid, const float* __restrict__ x,
                                           const float* __restrict__ W1) {
    __shared__ float      xs[256 * 17];    // stride 17: conflict-free
    __shared__ ulonglong2 ws2[16 * 4];     // W chunk 16x16 as f32x2 pairs
    int tid  = threadIdx.x;
    int row0 = gbid * 256;
    int rows = min(256, N_NODES - row0);
    bool v1  = tid < rows;

    unsigned long long acc[8];
    #pragma unroll
    for (int j = 0; j < 8; j++) acc[j] = 0ULL;

    for (int c = 0; c < IN_F / 16; c++) {
        if (tid < 64) ws2[tid] = ((const ulonglong2*)(W1 + c * 16 * HID))[tid];
        // X tile: rows x 16 floats = rows*4 float4
        for (int idx = tid; idx < rows * 4; idx += 256) {
            int r = idx >> 2, k4 = (idx & 3) * 4;
            float4 v = *(const float4*)(x + (size_t)(row0 + r) * IN_F + c * 16 + k4);
            int b = r * 17 + k4;
            xs[b] = v.x; xs[b + 1] = v.y; xs[b + 2] = v.z; xs[b + 3] = v.w;
        }
        __syncthreads();
        int base = tid * 17;
        #pragma unroll 4
        for (int k = 0; k < 16; k++) {
            unsigned long long xa = bcast2(v1 ? xs[base + k] : 0.f);
            ulonglong2 w0 = ws2[k * 4 + 0], w1 = ws2[k * 4 + 1];
            ulonglong2 w2 = ws2[k * 4 + 2], w3 = ws2[k * 4 + 3];
            acc[0] = fma2(w0.x, xa, acc[0]); acc[1] = fma2(w0.y, xa, acc[1]);
            acc[2] = fma2(w1.x, xa, acc[2]); acc[3] = fma2(w1.y, xa, acc[3]);
            acc[4] = fma2(w2.x, xa, acc[4]); acc[5] = fma2(w2.y, xa, acc[5]);
            acc[6] = fma2(w3.x, xa, acc[6]); acc[7] = fma2(w3.y, xa, acc[7]);
        }
        __syncthreads();
    }
    if (v1) {
        int r = row0 + tid;
        #pragma unroll
        for (int j = 0; j < 4; j++) {
            float2 a = unpack2(acc[2 * j]), b = unpack2(acc[2 * j + 1]);
            g_h1v[r * 4 + j] = make_float4(a.x, a.y, b.x, b.y);
        }
    }
}

// ---------------- K1: zero cnt + dtype detect (block-partitioned) -----------
__global__ void __launch_bounds__(256) k_zero_detect(const int* __restrict__ ei32) {
    if (blockIdx.x < 391) {
        int i = blockIdx.x * 256 + threadIdx.x;
        if (i < N_NODES) g_cnt[i] = 0;
    } else {
        __shared__ int found;
        if (threadIdx.x == 0) found = 0;
        __syncthreads();
        for (int k = threadIdx.x; k < 4096; k += 256) {
            long long idx = (1LL + (long long)k * 781LL) | 1LL;   // odd words
            if (idx < 2LL * N_EDGES && ei32[idx] != 0) found = 1;
        }
        __syncthreads();
        if (threadIdx.x == 0) g_is64 = (found == 0);
    }
}

// ---------------- K2: hist + gemm part 1 ------------------------------------
__global__ void __launch_bounds__(256) k_hist_gemm(const int* __restrict__ ei32,
                                                   const float* __restrict__ x,
                                                   const float* __restrict__ W1) {
    if (blockIdx.x < G1_GEMM) { gemm_block(blockIdx.x, x, W1); return; }
    int b = blockIdx.x - G1_GEMM;
    int is64 = g_is64;
    for (long long i = (long long)b * 256 + threadIdx.x; i < N_EDGES;
         i += (long long)HIST_B * 256) {
        int d = is64 ? ei32[2LL * N_EDGES + 2LL * i] : ei32[N_EDGES + i];
        if ((unsigned)d < N_NODES) atomicAdd(&g_cnt[d], 1);
    }
}

// ---------------- K3: scan phase A (tile sums + fused dinv) -----------------
__global__ void __launch_bounds__(1024) k_scanA() {
    __shared__ int sh[32];
    int t = threadIdx.x, lane = t & 31, wid = t >> 5;
    long long i = (long long)blockIdx.x * 1024 + t;
    int v = (i < N_NODES) ? g_cnt[i] : 0;
    if (i < N_NODES) g_dinv[i] = rsqrtf((float)(v + 1));
    int s = v;
    #pragma unroll
    for (int d = 16; d > 0; d >>= 1) s += __shfl_xor_sync(0xffffffffu, s, d);
    if (lane == 0) sh[wid] = s;
    __syncthreads();
    if (wid == 0) {
        int w = sh[lane];
        #pragma unroll
        for (int d = 16; d > 0; d >>= 1) w += __shfl_xor_sync(0xffffffffu, w, d);
        if (lane == 0) g_bsum[blockIdx.x] = w;
    }
}

// ---------------- K4: scan phase C with inlined tile-offset scan ------------
__global__ void __launch_bounds__(1024) k_scanC() {
    __shared__ int sh[32];
    __shared__ int boff_s;
    int t = threadIdx.x, lane = t & 31, wid = t >> 5;
    // warp 0: this block's exclusive offset = sum of g_bsum[0..blockIdx.x)
    if (wid == 0) {
        int s = 0;
        for (int i = lane; i < blockIdx.x; i += 32) s += g_bsum[i];
        #pragma unroll
        for (int d = 16; d > 0; d >>= 1) s += __shfl_xor_sync(0xffffffffu, s, d);
        if (lane == 0) boff_s = s;
    }
    long long i = (long long)blockIdx.x * 1024 + t;
    int v = (i < N_NODES) ? g_cnt[i] : 0;
    int x = v;
    #pragma unroll
    for (int d = 1; d < 32; d <<= 1) {
        int tt = __shfl_up_sync(0xffffffffu, x, d);
        if (lane >= d) x += tt;
    }
    if (lane == 31) sh[wid] = x;
    __syncthreads();
    if (wid == 0) {
        int w = sh[lane];
        #pragma unroll
        for (int d = 1; d < 32; d <<= 1) {
            int tt = __shfl_up_sync(0xffffffffu, w, d);
            if (lane >= d) w += tt;
        }
        sh[lane] = w;
    }
    __syncthreads();
    if (i < N_NODES) {
        int excl = boff_s + (wid > 0 ? sh[wid - 1] : 0) + x - v;
        g_rowptr[i]  = excl;
        g_rowfill[i] = excl;
    }
}

// ---------------- K5: scatter + gemm part 2 ---------------------------------
__global__ void __launch_bounds__(256) k_scatter_gemm(const int* __restrict__ ei32,
                                                      const float* __restrict__ x,
                                                      const float* __restrict__ W1) {
    if (blockIdx.x < (G_GEMM - G1_GEMM)) {
        gemm_block(G1_GEMM + blockIdx.x, x, W1);
        return;
    }
    int b = blockIdx.x - (G_GEMM - G1_GEMM);
    int is64 = g_is64;
    for (long long i = (long long)b * 256 + threadIdx.x; i < N_EDGES;
         i += (long long)SCAT_B * 256) {
        int s, d;
        if (is64) {
            s = ei32[2LL * i];
            d = ei32[2LL * N_EDGES + 2LL * i];
        } else {
            s = ei32[i];
            d = ei32[N_EDGES + i];
        }
        if ((unsigned)s < N_NODES && (unsigned)d < N_NODES) {
            int pos = atomicAdd(&g_rowfill[d], 1);
            if ((unsigned)pos < N_EDGES) {
                float w = g_dinv[s] * g_dinv[d];
                g_edges[pos] = make_int2(s, __float_as_int(w));
            }
        }
    }
}

// ---------------- K6: agg layer 1 + bias + relu + GEMM2 fused ---------------
__global__ void __launch_bounds__(256) k_agg1(const float* __restrict__ b1,
                                              const float* __restrict__ W2) {
    __shared__ float W2s[HID * 8];   // padded cols, col 7 = 0
    __shared__ float b1s[HID];
    int tid = threadIdx.x;
    if (tid < 128) {
        int f = tid >> 3, j = tid & 7;
        W2s[tid] = (j < NCLS) ? W2[f * NCLS + j] : 0.f;
    }
    if (tid < HID) b1s[tid] = b1[tid];
    __syncthreads();

    const float* h1 = (const float*)g_h1v;
    int warp = tid >> 5, lane = tid & 31;
    int node = blockIdx.x * 8 + warp;
    if (node >= N_NODES) return;

    int start = g_rowptr[node];
    int cnt   = g_cnt[node];
    int f = lane & 15, half = lane >> 4;

    float acc = 0.f;
    for (int e = start + half; e < start + cnt; e += 2) {
        int2 ed = g_edges[e];
        unsigned s = (unsigned)ed.x;
        if (s < N_NODES) acc += h1[(size_t)s * HID + f] * __int_as_float(ed.y);
    }
    acc += __shfl_xor_sync(0xffffffffu, acc, 16);

    float di = g_dinv[node];
    acc += h1[(size_t)node * HID + f] * di * di;
    acc = fmaxf(acc + b1s[f], 0.f);

    float hj = 0.f;
    #pragma unroll
    for (int ff = 0; ff < HID; ff++) {
        float a = __shfl_sync(0xffffffffu, acc, ff);
        hj += a * W2s[ff * 8 + (lane & 7)];
    }
    if (lane < 8) g_h2[(size_t)node * 8 + lane] = hj;
}

// ---------------- K7: agg layer 2 + bias + log_softmax ----------------------
__global__ void __launch_bounds__(256) k_agg2(const float* __restrict__ b2,
                                              float* __restrict__ out) {
    __shared__ float b2s[8];
    int tid = threadIdx.x;
    if (tid < 8) b2s[tid] = (tid < NCLS) ? b2[tid] : 0.f;
    __syncthreads();

    int warp = tid >> 5, lane = tid & 31;
    int node = blockIdx.x * 8 + warp;
    if (node >= N_NODES) return;

    int start = g_rowptr[node];
    int cnt   = g_cnt[node];
    int j = lane & 7, q = lane >> 3;

    float acc = 0.f;
    for (int e = start + q; e < start + cnt; e += 4) {
        int2 ed = g_edges[e];
        unsigned s = (unsigned)ed.x;
        if (s < N_NODES) acc += g_h2[(size_t)s * 8 + j] * __int_as_float(ed.y);
    }
    acc += __shfl_xor_sync(0xffffffffu, acc, 16);
    acc += __shfl_xor_sync(0xffffffffu, acc, 8);

    float di = g_dinv[node];
    acc += g_h2[(size_t)node * 8 + j] * di * di + b2s[j];

    float v = (j < NCLS) ? acc : -1e30f;
    float m = v;
    m = fmaxf(m, __shfl_xor_sync(0xffffffffu, m, 4));
    m = fmaxf(m, __shfl_xor_sync(0xffffffffu, m, 2));
    m = fmaxf(m, __shfl_xor_sync(0xffffffffu, m, 1));
    float ex = (j < NCLS) ? expf(v - m) : 0.f;
    float s = ex;
    s += __shfl_xor_sync(0xffffffffu, s, 4);
    s += __shfl_xor_sync(0xffffffffu, s, 2);
    s += __shfl_xor_sync(0xffffffffu, s, 1);
    if (j < NCLS) out[(size_t)node * NCLS + j] = v - m - logf(s);
}

// ---------------- launch ----------------------------------------------------
extern "C" void kernel_launch(void* const* d_in, const int* in_sizes, int n_in,
                              void* d_out, int out_size) {
    const float* x  = nullptr;
    const int*   ei = nullptr;     // int32 view; dtype auto-detected on device
    const float* W1 = nullptr;
    const float* b1 = nullptr;
    const float* W2 = nullptr;
    const float* b2 = nullptr;

    for (int i = 0; i < n_in; i++) {
        long long sz = in_sizes[i];
        if      (sz == (long long)N_NODES * IN_F)                 x  = (const float*)d_in[i];
        else if (sz == 2LL * N_EDGES || sz == 4LL * N_EDGES)      ei = (const int*)d_in[i];
        else if (sz == (long long)IN_F * HID)                     W1 = (const float*)d_in[i];
        else if (sz == HID)                                       b1 = (const float*)d_in[i];
        else if (sz == (long long)HID * NCLS)                     W2 = (const float*)d_in[i];
        else if (sz == NCLS)                                      b2 = (const float*)d_in[i];
    }
    if (!x || !ei || !W1 || !b1 || !W2 || !b2) return;
    float* out = (float*)d_out;

    k_zero_detect<<<392, 256>>>(ei);
    k_hist_gemm<<<G1_GEMM + HIST_B, 256>>>(ei, x, W1);
    k_scanA<<<NB, 1024>>>();
    k_scanC<<<NB, 1024>>>();
    k_scatter_gemm<<<(G_GEMM - G1_GEMM) + SCAT_B, 256>>>(ei, x, W1);
    k_agg1<<<(N_NODES + 7) / 8, 256>>>(b1, W2);
    k_agg2<<<(N_NODES + 7) / 8, 256>>>(b2, out);
}

// round 10
// speedup vs baseline: 1.3846x; 1.3846x over previous
#include <cuda_runtime.h>
#include <cuda_bf16.h>
#include <cstdint>
#include <math.h>

#define N_NODES 100000
#define N_EDGES 1600000
#define IN_F    512
#define HID     16
#define NCLS    7
#define NB      98            // ceil(N_NODES / 1024) scan tiles

// ---------------- scratch (static device globals; no runtime allocation) ----
__device__ float4 g_h1v[N_NODES * 4];      // dinv*X@W1, 16 floats/node (6.4 MB)
__device__ float  g_h2[N_NODES * 8];       // dinv*(layer-2 feats), padded to 8
__device__ float  g_dinv[N_NODES];         // D^-1/2
__device__ int    g_cnt[N_NODES];          // in-degree (excl. self loop)
__device__ int    g_rowptr[N_NODES];       // CSR row starts (by dst)
__device__ int    g_rowfill[N_NODES];      // scatter cursors
__device__ int    g_esrc[N_EDGES];         // src only, grouped by dst (6.4 MB)
__device__ int    g_is64;                  // edge_index dtype flag
__device__ int    g_bsum[128];             // per-scan-tile sums

// ---------------- f32x2 helpers ---------------------------------------------
__device__ __forceinline__ unsigned long long fma2(unsigned long long a,
                                                   unsigned long long b,
                                                   unsigned long long c) {
    unsigned long long d;
    asm("fma.rn.f32x2 %0, %1, %2, %3;" : "=l"(d) : "l"(a), "l"(b), "l"(c));
    return d;
}
__device__ __forceinline__ unsigned long long bcast2(float v) {
    unsigned long long d;
    asm("mov.b64 %0, {%1, %1};" : "=l"(d) : "f"(v));
    return d;
}
__device__ __forceinline__ float2 unpack2(unsigned long long v) {
    float2 r;
    asm("mov.b64 {%0, %1}, %2;" : "=f"(r.x), "=f"(r.y) : "l"(v));
    return r;
}

// ---------------- K1: zero cnt + dtype detect (block-partitioned) -----------
__global__ void __launch_bounds__(256) k_zero_detect(const int* __restrict__ ei32) {
    if (blockIdx.x < 391) {
        int i = blockIdx.x * 256 + threadIdx.x;
        if (i < N_NODES) g_cnt[i] = 0;
    } else {
        __shared__ int found;
        if (threadIdx.x == 0) found = 0;
        __syncthreads();
        for (int k = threadIdx.x; k < 4096; k += 256) {
            long long idx = (1LL + (long long)k * 781LL) | 1LL;   // odd words
            if (idx < 2LL * N_EDGES && ei32[idx] != 0) found = 1;
        }
        __syncthreads();
        if (threadIdx.x == 0) g_is64 = (found == 0);
    }
}

// ---------------- K2: hist ---------------------------------------------------
__global__ void __launch_bounds__(256) k_hist(const int* __restrict__ ei32) {
    int i = blockIdx.x * blockDim.x + threadIdx.x;
    if (i < N_EDGES) {
        int d = g_is64 ? ei32[2LL * N_EDGES + 2LL * i] : ei32[N_EDGES + i];
        if ((unsigned)d < N_NODES) atomicAdd(&g_cnt[d], 1);
    }
}

// ---------------- K3: scan phase A (tile sums + fused dinv) -----------------
__global__ void __launch_bounds__(1024) k_scanA() {
    __shared__ int sh[32];
    int t = threadIdx.x, lane = t & 31, wid = t >> 5;
    long long i = (long long)blockIdx.x * 1024 + t;
    int v = (i < N_NODES) ? g_cnt[i] : 0;
    if (i < N_NODES) g_dinv[i] = rsqrtf((float)(v + 1));
    int s = v;
    #pragma unroll
    for (int d = 16; d > 0; d >>= 1) s += __shfl_xor_sync(0xffffffffu, s, d);
    if (lane == 0) sh[wid] = s;
    __syncthreads();
    if (wid == 0) {
        int w = sh[lane];
        #pragma unroll
        for (int d = 16; d > 0; d >>= 1) w += __shfl_xor_sync(0xffffffffu, w, d);
        if (lane == 0) g_bsum[blockIdx.x] = w;
    }
}

// ---------------- K4: scan phase C with inlined tile-offset scan ------------
__global__ void __launch_bounds__(1024) k_scanC() {
    __shared__ int sh[32];
    __shared__ int boff_s;
    int t = threadIdx.x, lane = t & 31, wid = t >> 5;
    if (wid == 0) {
        int s = 0;
        for (int i = lane; i < blockIdx.x; i += 32) s += g_bsum[i];
        #pragma unroll
        for (int d = 16; d > 0; d >>= 1) s += __shfl_xor_sync(0xffffffffu, s, d);
        if (lane == 0) boff_s = s;
    }
    long long i = (long long)blockIdx.x * 1024 + t;
    int v = (i < N_NODES) ? g_cnt[i] : 0;
    int x = v;
    #pragma unroll
    for (int d = 1; d < 32; d <<= 1) {
        int tt = __shfl_up_sync(0xffffffffu, x, d);
        if (lane >= d) x += tt;
    }
    if (lane == 31) sh[wid] = x;
    __syncthreads();
    if (wid == 0) {
        int w = sh[lane];
        #pragma unroll
        for (int d = 1; d < 32; d <<= 1) {
            int tt = __shfl_up_sync(0xffffffffu, w, d);
            if (lane >= d) w += tt;
        }
        sh[lane] = w;
    }
    __syncthreads();
    if (i < N_NODES) {
        int excl = boff_s + (wid > 0 ? sh[wid - 1] : 0) + x - v;
        g_rowptr[i]  = excl;
        g_rowfill[i] = excl;
    }
}

// ---------------- K5: scatter (src only, 4B entries) ------------------------
__global__ void __launch_bounds__(256) k_scatter(const int* __restrict__ ei32) {
    int i = blockIdx.x * blockDim.x + threadIdx.x;
    if (i < N_EDGES) {
        int s, d;
        if (g_is64) {
            s = ei32[2LL * i];
            d = ei32[2LL * N_EDGES + 2LL * i];
        } else {
            s = ei32[i];
            d = ei32[N_EDGES + i];
        }
        if ((unsigned)s < N_NODES && (unsigned)d < N_NODES) {
            int pos = atomicAdd(&g_rowfill[d], 1);
            if ((unsigned)pos < N_EDGES) g_esrc[pos] = s;
        }
    }
}

// ---------------- K6: GEMM1 h1' = dinv * (X @ W1) ---------------------------
// 128 threads, 256 rows/block (2 rows/thread), K chunked by 32, f32x2 FMA.
__global__ void __launch_bounds__(128) k_gemm1(const float* __restrict__ x,
                                               const float* __restrict__ W1) {
    __shared__ float      xs[256 * 33];    // 33 stride: conflict-free
    __shared__ ulonglong2 ws2[32 * 4];     // W chunk 32x16 as f32x2 pairs
    int tid  = threadIdx.x;
    int row0 = blockIdx.x * 256;
    int rows = min(256, N_NODES - row0);
    bool v1 = tid < rows;
    bool v2 = tid + 128 < rows;

    unsigned long long acc1[8], acc2[8];
    #pragma unroll
    for (int j = 0; j < 8; j++) { acc1[j] = 0ULL; acc2[j] = 0ULL; }

    for (int c = 0; c < IN_F / 32; c++) {
        ws2[tid] = ((const ulonglong2*)(W1 + c * 32 * HID))[tid];
        for (int idx = tid; idx < rows * 8; idx += 128) {
            int r = idx >> 3, k4 = (idx & 7) * 4;
            float4 v = *(const float4*)(x + (size_t)(row0 + r) * IN_F + c * 32 + k4);
            int b = r * 33 + k4;
            xs[b] = v.x; xs[b + 1] = v.y; xs[b + 2] = v.z; xs[b + 3] = v.w;
        }
        __syncthreads();
        int base1 = tid * 33, base2 = (tid + 128) * 33;
        #pragma unroll 4
        for (int k = 0; k < 32; k++) {
            unsigned long long xa = bcast2(v1 ? xs[base1 + k] : 0.f);
            unsigned long long xb = bcast2(v2 ? xs[base2 + k] : 0.f);
            ulonglong2 w0 = ws2[k * 4 + 0], w1 = ws2[k * 4 + 1];
            ulonglong2 w2 = ws2[k * 4 + 2], w3 = ws2[k * 4 + 3];
            acc1[0] = fma2(w0.x, xa, acc1[0]); acc1[1] = fma2(w0.y, xa, acc1[1]);
            acc1[2] = fma2(w1.x, xa, acc1[2]); acc1[3] = fma2(w1.y, xa, acc1[3]);
            acc1[4] = fma2(w2.x, xa, acc1[4]); acc1[5] = fma2(w2.y, xa, acc1[5]);
            acc1[6] = fma2(w3.x, xa, acc1[6]); acc1[7] = fma2(w3.y, xa, acc1[7]);
            acc2[0] = fma2(w0.x, xb, acc2[0]); acc2[1] = fma2(w0.y, xb, acc2[1]);
            acc2[2] = fma2(w1.x, xb, acc2[2]); acc2[3] = fma2(w1.y, xb, acc2[3]);
            acc2[4] = fma2(w2.x, xb, acc2[4]); acc2[5] = fma2(w2.y, xb, acc2[5]);
            acc2[6] = fma2(w3.x, xb, acc2[6]); acc2[7] = fma2(w3.y, xb, acc2[7]);
        }
        __syncthreads();
    }
    if (v1) {
        int r = row0 + tid;
        float di = g_dinv[r];
        #pragma unroll
        for (int j = 0; j < 4; j++) {
            float2 a = unpack2(acc1[2 * j]), b = unpack2(acc1[2 * j + 1]);
            g_h1v[r * 4 + j] = make_float4(a.x * di, a.y * di, b.x * di, b.y * di);
        }
    }
    if (v2) {
        int r = row0 + tid + 128;
        float di = g_dinv[r];
        #pragma unroll
        for (int j = 0; j < 4; j++) {
            float2 a = unpack2(acc2[2 * j]), b = unpack2(acc2[2 * j + 1]);
            g_h1v[r * 4 + j] = make_float4(a.x * di, a.y * di, b.x * di, b.y * di);
        }
    }
}

// ---------------- K7: agg layer 1 + bias + relu + GEMM2 (+dinv scale) -------
// warp per node: 2 half-warps x 16 features, 2 edges/iter.
__global__ void __launch_bounds__(256) k_agg1(const float* __restrict__ b1,
                                              const float* __restrict__ W2) {
    __shared__ float W2s[HID * 8];   // padded cols, col 7 = 0
    __shared__ float b1s[HID];
    int tid = threadIdx.x;
    if (tid < 128) {
        int f = tid >> 3, j = tid & 7;
        W2s[tid] = (j < NCLS) ? W2[f * NCLS + j] : 0.f;
    }
    if (tid < HID) b1s[tid] = b1[tid];
    __syncthreads();

    const float* h1 = (const float*)g_h1v;
    int warp = tid >> 5, lane = tid & 31;
    int node = blockIdx.x * 8 + warp;
    if (node >= N_NODES) return;

    int start = g_rowptr[node];
    int cnt   = g_cnt[node];
    int f = lane & 15, half = lane >> 4;

    float acc = 0.f;
    for (int e = start + half; e < start + cnt; e += 2) {
        unsigned s = (unsigned)g_esrc[e];
        if (s < N_NODES) acc += h1[(size_t)s * HID + f];
    }
    acc += __shfl_xor_sync(0xffffffffu, acc, 16);

    float di = g_dinv[node];
    acc += h1[(size_t)node * HID + f];           // self loop (already dinv-scaled)
    acc = fmaxf(acc * di + b1s[f], 0.f);         // factor dinv[d], + bias, relu

    // GEMM2 + dinv scale for layer-2 aggregation
    float hj = 0.f;
    #pragma unroll
    for (int ff = 0; ff < HID; ff++) {
        float a = __shfl_sync(0xffffffffu, acc, ff);
        hj += a * W2s[ff * 8 + (lane & 7)];
    }
    if (lane < 8) g_h2[(size_t)node * 8 + lane] = hj * di;   // h2' = dinv*h2
}

// ---------------- K8: agg layer 2 + bias + log_softmax ----------------------
__global__ void __launch_bounds__(256) k_agg2(const float* __restrict__ b2,
                                              float* __restrict__ out) {
    __shared__ float b2s[8];
    int tid = threadIdx.x;
    if (tid < 8) b2s[tid] = (tid < NCLS) ? b2[tid] : 0.f;
    __syncthreads();

    int warp = tid >> 5, lane = tid & 31;
    int node = blockIdx.x * 8 + warp;
    if (node >= N_NODES) return;

    int start = g_rowptr[node];
    int cnt   = g_cnt[node];
    int j = lane & 7, q = lane >> 3;

    float acc = 0.f;
    for (int e = start + q; e < start + cnt; e += 4) {
        unsigned s = (unsigned)g_esrc[e];
        if (s < N_NODES) acc += g_h2[(size_t)s * 8 + j];
    }
    acc += __shfl_xor_sync(0xffffffffu, acc, 16);
    acc += __shfl_xor_sync(0xffffffffu, acc, 8);

    float di = g_dinv[node];
    acc = (acc + g_h2[(size_t)node * 8 + j]) * di + b2s[j];

    float v = (j < NCLS) ? acc : -1e30f;
    float m = v;
    m = fmaxf(m, __shfl_xor_sync(0xffffffffu, m, 4));
    m = fmaxf(m, __shfl_xor_sync(0xffffffffu, m, 2));
    m = fmaxf(m, __shfl_xor_sync(0xffffffffu, m, 1));
    float ex = (j < NCLS) ? expf(v - m) : 0.f;
    float s = ex;
    s += __shfl_xor_sync(0xffffffffu, s, 4);
    s += __shfl_xor_sync(0xffffffffu, s, 2);
    s += __shfl_xor_sync(0xffffffffu, s, 1);
    if (j < NCLS) out[(size_t)node * NCLS + j] = v - m - logf(s);
}

// ---------------- launch ----------------------------------------------------
extern "C" void kernel_launch(void* const* d_in, const int* in_sizes, int n_in,
                              void* d_out, int out_size) {
    const float* x  = nullptr;
    const int*   ei = nullptr;     // int32 view; dtype auto-detected on device
    const float* W1 = nullptr;
    const float* b1 = nullptr;
    const float* W2 = nullptr;
    const float* b2 = nullptr;

    for (int i = 0; i < n_in; i++) {
        long long sz = in_sizes[i];
        if      (sz == (long long)N_NODES * IN_F)                 x  = (const float*)d_in[i];
        else if (sz == 2LL * N_EDGES || sz == 4LL * N_EDGES)      ei = (const int*)d_in[i];
        else if (sz == (long long)IN_F * HID)                     W1 = (const float*)d_in[i];
        else if (sz == HID)                                       b1 = (const float*)d_in[i];
        else if (sz == (long long)HID * NCLS)                     W2 = (const float*)d_in[i];
        else if (sz == NCLS)                                      b2 = (const float*)d_in[i];
    }
    if (!x || !ei || !W1 || !b1 || !W2 || !b2) return;
    float* out = (float*)d_out;

    k_zero_detect<<<392, 256>>>(ei);
    k_hist<<<(N_EDGES + 255) / 256, 256>>>(ei);
    k_scanA<<<NB, 1024>>>();
    k_scanC<<<NB, 1024>>>();
    k_scatter<<<(N_EDGES + 255) / 256, 256>>>(ei);
    k_gemm1<<<(N_NODES + 255) / 256, 128>>>(x, W1);
    k_agg1<<<(N_NODES + 7) / 8, 256>>>(b1, W2);
    k_agg2<<<(N_NODES + 7) / 8, 256>>>(b2, out);
}